// round 6
// baseline (speedup 1.0000x reference)
#include <cuda_runtime.h>
#include <cuda_fp16.h>
#include <cstdint>

#define T_STEPS 300
#define BATCH   256
#define NIN     128
#define NH      512
#define NOUT    3
#define DTSEC   0.01f
#define ALPHA_N 0.2f

#define Y_SIZE (BATCH * T_STEPS * NOUT)

// ---------------- device scratch (static, allocation-free) ----------------
__device__ float     g_drive[(size_t)T_STEPS * BATCH * NH];   // 157 MB
__device__ uint32_t  g_wrnnp[(NH / 2) * NH];                  // packed half2 (k-pair x h)
__device__ uint32_t  g_winp[(NIN / 2) * NH];
__device__ float     g_wout[NH * NOUT];
__device__ __half    g_rpost[2 * BATCH * NH];                 // double-buffered activations
__device__ float     g_yraw[(size_t)T_STEPS * BATCH * NOUT];

__device__ __forceinline__ uint32_t smem_u32(const void* p) {
    uint32_t a;
    asm("{ .reg .u64 t; cvta.to.shared.u64 t, %1; cvt.u32.u64 %0, t; }" : "=r"(a) : "l"(p));
    return a;
}

// ---------------- prep -----------------------------------------------------
__global__ void prep_kernel(const float* __restrict__ w_in, const float* __restrict__ w_in_mask,
                            const float* __restrict__ w_rnn_base, const float* __restrict__ conn,
                            const float* __restrict__ ei, const float* __restrict__ w_out,
                            const float* __restrict__ w_out_mask)
{
    int tid = blockIdx.x * blockDim.x + threadIdx.x;
    int nth = gridDim.x * blockDim.x;

    for (int i = tid; i < (NH / 2) * NH; i += nth) {
        int p = i >> 9, h = i & (NH - 1);
        int k0 = 2 * p, k1 = 2 * p + 1;
        float s0 = ei[k0 * NH + k0];
        float s1 = ei[k1 * NH + k1];
        float v0 = fmaxf(w_rnn_base[k0 * NH + h] * conn[k0 * NH + h], 0.f) * s0;
        float v1 = fmaxf(w_rnn_base[k1 * NH + h] * conn[k1 * NH + h], 0.f) * s1;
        __half2 hv = __floats2half2_rn(v0, v1);
        g_wrnnp[i] = *reinterpret_cast<uint32_t*>(&hv);
    }
    for (int i = tid; i < (NIN / 2) * NH; i += nth) {
        int p = i >> 9, h = i & (NH - 1);
        float v0 = w_in[(2 * p) * NH + h] * w_in_mask[(2 * p) * NH + h];
        float v1 = w_in[(2 * p + 1) * NH + h] * w_in_mask[(2 * p + 1) * NH + h];
        __half2 hv = __floats2half2_rn(v0, v1);
        g_winp[i] = *reinterpret_cast<uint32_t*>(&hv);
    }
    for (int i = tid; i < NH * NOUT; i += nth)
        g_wout[i] = fmaxf(w_out[i] * w_out_mask[i], 0.f);
}

// ---------------- drive GEMM: drive = 0.2*(inp@w_in_eff + b_rnn) + noise ---
__global__ void __launch_bounds__(256) drive_gemm(const float* __restrict__ inp,
                                                  const float* __restrict__ noise,
                                                  const float* __restrict__ b_rnn)
{
    __shared__ __half   a_s[64 * 136];
    __shared__ uint32_t b_s[64 * 68];

    int row0 = blockIdx.x * 64;
    int n0   = blockIdx.y * 64;
    int tid  = threadIdx.x;

    #pragma unroll
    for (int j = 0; j < 32; j++) {
        int idx = tid + j * 256;
        int i = idx >> 7, k = idx & 127;
        a_s[i * 136 + k] = __float2half_rn(inp[(size_t)(row0 + i) * NIN + k]);
    }
    #pragma unroll
    for (int j = 0; j < 16; j++) {
        int idx = tid + j * 256;
        int p = idx >> 6, c = idx & 63;
        b_s[p * 68 + c] = g_winp[p * NH + n0 + c];
    }
    __syncthreads();

    int w = tid >> 5, lane = tid & 31;
    int g = lane >> 2, t = lane & 3;
    int m0 = (w & 3) * 16;
    int nw = (w >> 2) * 32;

    float acc[4][4] = {};
    #pragma unroll
    for (int kk = 0; kk < 8; kk++) {
        int k0 = kk * 16;
        uint32_t a0 = *reinterpret_cast<const uint32_t*>(&a_s[(m0 + g) * 136 + k0 + 2 * t]);
        uint32_t a1 = *reinterpret_cast<const uint32_t*>(&a_s[(m0 + g + 8) * 136 + k0 + 2 * t]);
        uint32_t a2 = *reinterpret_cast<const uint32_t*>(&a_s[(m0 + g) * 136 + k0 + 8 + 2 * t]);
        uint32_t a3 = *reinterpret_cast<const uint32_t*>(&a_s[(m0 + g + 8) * 136 + k0 + 8 + 2 * t]);
        #pragma unroll
        for (int s = 0; s < 4; s++) {
            int col = nw + 8 * s + g;
            uint32_t b0 = b_s[(kk * 8 + t) * 68 + col];
            uint32_t b1 = b_s[(kk * 8 + t + 4) * 68 + col];
            asm volatile("mma.sync.aligned.m16n8k16.row.col.f32.f16.f16.f32 "
                         "{%0,%1,%2,%3}, {%4,%5,%6,%7}, {%8,%9}, {%0,%1,%2,%3};"
                         : "+f"(acc[s][0]), "+f"(acc[s][1]), "+f"(acc[s][2]), "+f"(acc[s][3])
                         : "r"(a0), "r"(a1), "r"(a2), "r"(a3), "r"(b0), "r"(b1));
        }
    }

    #pragma unroll
    for (int s = 0; s < 4; s++) {
        int gc  = n0 + nw + 8 * s + 2 * t;
        float br0 = b_rnn[gc], br1 = b_rnn[gc + 1];
        int r0 = row0 + m0 + g;
        int r1 = r0 + 8;
        float2 nz0 = *reinterpret_cast<const float2*>(&noise[(size_t)r0 * NH + gc]);
        float2 nz1 = *reinterpret_cast<const float2*>(&noise[(size_t)r1 * NH + gc]);
        float2 d0, d1;
        d0.x = ALPHA_N * (acc[s][0] + br0) + nz0.x;
        d0.y = ALPHA_N * (acc[s][1] + br1) + nz0.y;
        d1.x = ALPHA_N * (acc[s][2] + br0) + nz1.x;
        d1.y = ALPHA_N * (acc[s][3] + br1) + nz1.y;
        *reinterpret_cast<float2*>(&g_drive[(size_t)r0 * NH + gc]) = d0;
        *reinterpret_cast<float2*>(&g_drive[(size_t)r1 * NH + gc]) = d1;
    }
}

// ---------------- persistent step kernel -----------------------------------
// 128 CTAs = 16 clusters of 8 (one cluster per 16-row batch group).
// W_rnn B-fragments in registers; data exchange via L2; signaling via
// cluster mbarrier (fire-and-forget remote arrives + HW-sleep local wait).
__global__ void __launch_bounds__(256, 1) __cluster_dims__(8, 1, 1) step_kernel(
    const float* __restrict__ x_init, const float* __restrict__ sx_init,
    const float* __restrict__ su_init,
    const float* __restrict__ a_std, const float* __restrict__ a_stf,
    const float* __restrict__ Uv, const float* __restrict__ dynv,
    float* __restrict__ out_x)
{
    __shared__ __half rp[16 * 520];      // staged rpost tile [16][520]
    __shared__ uint64_t mbar;

    int cta   = blockIdx.x;
    int grp   = cta >> 3;
    int slice = cta & 7;
    int b0 = grp * 16;
    int h0 = slice * 64;
    int tid = threadIdx.x;
    int w = tid >> 5, lane = tid & 31;
    int g = lane >> 2, t = lane & 3;

    uint32_t mbar_addr = smem_u32(&mbar);
    if (tid == 0)
        asm volatile("mbarrier.init.shared.b64 [%0], 8;" :: "r"(mbar_addr) : "memory");

    // ---- persistent B fragments for W_rnn slice (registers, step-invariant)
    uint32_t breg0[32], breg1[32];
    {
        int c = h0 + 8 * w + g;
        #pragma unroll
        for (int kk = 0; kk < 32; kk++) {
            breg0[kk] = g_wrnnp[(size_t)(kk * 8 + t) * NH + c];
            breg1[kk] = g_wrnnp[(size_t)(kk * 8 + t + 4) * NH + c];
        }
    }

    int hb  = h0 + 8 * w + 2 * t;
    int br0 = b0 + g, br1 = b0 + g + 8;

    float as0 = a_std[hb], as1 = a_std[hb + 1];
    float af0 = a_stf[hb], af1 = a_stf[hb + 1];
    float U0  = Uv[hb],    U1  = Uv[hb + 1];
    float dy0 = dynv[hb],  dy1 = dynv[hb + 1];

    float x0 = x_init[br0 * NH + hb],   x1 = x_init[br0 * NH + hb + 1];
    float x2 = x_init[br1 * NH + hb],   x3 = x_init[br1 * NH + hb + 1];
    float sx0 = sx_init[br0 * NH + hb], sx1 = sx_init[br0 * NH + hb + 1];
    float sx2 = sx_init[br1 * NH + hb], sx3 = sx_init[br1 * NH + hb + 1];
    float su0 = su_init[br0 * NH + hb], su1 = su_init[br0 * NH + hb + 1];
    float su2 = su_init[br1 * NH + hb], su3 = su_init[br1 * NH + hb + 1];

    __half2* rgl = reinterpret_cast<__half2*>(g_rpost);

    // ldmatrix lane address: row = lane&15, k-half offset for lanes 16-31
    uint32_t lds_a = smem_u32(rp) + (lane & 15) * (520 * 2) + ((lane >> 4) & 1) * 16;

    // cluster sync: all peers' mbarriers initialized before any remote arrive
    asm volatile("barrier.cluster.arrive.aligned;" ::: "memory");
    asm volatile("barrier.cluster.wait.aligned;"   ::: "memory");

    for (int ts = 0; ts < T_STEPS; ts++) {
        // ---- prefetch drive early (consumed ~2000cy later) ----
        float2 d0 = *reinterpret_cast<const float2*>(&g_drive[((size_t)ts * BATCH + br0) * NH + hb]);
        float2 d1 = *reinterpret_cast<const float2*>(&g_drive[((size_t)ts * BATCH + br1) * NH + hb]);

        // ---- phase 1: STP update + x_post + rpost ----
        float xp0, xp1, xp2, xp3;
        {
            float r, sxn, sun;
            r = fmaxf(x0, 0.f);
            sxn = sx0 + (as0 * (1.f - sx0) - DTSEC * su0 * sx0 * r) * dy0;
            sun = su0 + (af0 * (U0 - su0) + DTSEC * U0 * (1.f - su0) * r) * dy0;
            sx0 = fminf(fmaxf(sxn, 0.f), 1.f); su0 = fminf(fmaxf(sun, 0.f), 1.f);
            xp0 = su0 * sx0 * x0;

            r = fmaxf(x1, 0.f);
            sxn = sx1 + (as1 * (1.f - sx1) - DTSEC * su1 * sx1 * r) * dy1;
            sun = su1 + (af1 * (U1 - su1) + DTSEC * U1 * (1.f - su1) * r) * dy1;
            sx1 = fminf(fmaxf(sxn, 0.f), 1.f); su1 = fminf(fmaxf(sun, 0.f), 1.f);
            xp1 = su1 * sx1 * x1;

            r = fmaxf(x2, 0.f);
            sxn = sx2 + (as0 * (1.f - sx2) - DTSEC * su2 * sx2 * r) * dy0;
            sun = su2 + (af0 * (U0 - su2) + DTSEC * U0 * (1.f - su2) * r) * dy0;
            sx2 = fminf(fmaxf(sxn, 0.f), 1.f); su2 = fminf(fmaxf(sun, 0.f), 1.f);
            xp2 = su2 * sx2 * x2;

            r = fmaxf(x3, 0.f);
            sxn = sx3 + (as1 * (1.f - sx3) - DTSEC * su3 * sx3 * r) * dy1;
            sun = su3 + (af1 * (U1 - su3) + DTSEC * U1 * (1.f - su3) * r) * dy1;
            sx3 = fminf(fmaxf(sxn, 0.f), 1.f); su3 = fminf(fmaxf(sun, 0.f), 1.f);
            xp3 = su3 * sx3 * x3;
        }
        int buf = ts & 1;
        rgl[(buf * BATCH * NH + br0 * NH + hb) >> 1] =
            __floats2half2_rn(fmaxf(xp0, 0.f), fmaxf(xp1, 0.f));
        rgl[(buf * BATCH * NH + br1 * NH + hb) >> 1] =
            __floats2half2_rn(fmaxf(xp2, 0.f), fmaxf(xp3, 0.f));

        // ---- publish: 8 fire-and-forget remote arrives (one per peer) ----
        __syncthreads();
        if (tid < 8) {
            uint32_t remote;
            asm volatile("mapa.shared::cluster.u32 %0, %1, %2;"
                         : "=r"(remote) : "r"(mbar_addr), "r"(tid));
            asm volatile("mbarrier.arrive.release.cluster.shared::cluster.b64 _, [%0];"
                         :: "r"(remote) : "memory");
        }

        // ---- wait: HW-sleep on local mbarrier (all threads) ----
        {
            uint32_t parity = ts & 1;
            uint32_t done = 0;
            while (!done)
                asm volatile("{ .reg .pred p; "
                             "mbarrier.try_wait.parity.acquire.cluster.shared::cta.b64 p, [%1], %2, 0x989680; "
                             "selp.b32 %0, 1, 0, p; }"
                             : "=r"(done) : "r"(mbar_addr), "r"(parity) : "memory");
        }

        // ---- stage rpost [16][512] fp16 via L2 (.cg skips L1) ----
        {
            const uint4* src = reinterpret_cast<const uint4*>(g_rpost + buf * BATCH * NH);
            #pragma unroll
            for (int j = 0; j < 4; j++) {
                int idx = tid + j * 256;
                int row = idx >> 6, c8 = idx & 63;
                uint4 v;
                asm volatile("ld.global.cg.v4.u32 {%0,%1,%2,%3}, [%4];"
                             : "=r"(v.x), "=r"(v.y), "=r"(v.z), "=r"(v.w)
                             : "l"(src + (size_t)(b0 + row) * 64 + c8));
                *reinterpret_cast<uint4*>(rp + row * 520 + c8 * 8) = v;
            }
        }
        __syncthreads();

        // ---- mma: C[16x64] = rpost[16x512] @ W[512x64]; 4 accumulator chains
        float acc[4][4] = {};
        #pragma unroll
        for (int kk = 0; kk < 32; kk++) {
            uint32_t a0, a1, a2, a3;
            asm volatile("ldmatrix.sync.aligned.m8n8.x4.shared.b16 {%0,%1,%2,%3}, [%4];"
                         : "=r"(a0), "=r"(a1), "=r"(a2), "=r"(a3)
                         : "r"(lds_a + kk * 32));
            float* A = acc[kk & 3];
            asm volatile("mma.sync.aligned.m16n8k16.row.col.f32.f16.f16.f32 "
                         "{%0,%1,%2,%3}, {%4,%5,%6,%7}, {%8,%9}, {%0,%1,%2,%3};"
                         : "+f"(A[0]), "+f"(A[1]), "+f"(A[2]), "+f"(A[3])
                         : "r"(a0), "r"(a1), "r"(a2), "r"(a3), "r"(breg0[kk]), "r"(breg1[kk]));
        }
        float s0 = (acc[0][0] + acc[1][0]) + (acc[2][0] + acc[3][0]);
        float s1 = (acc[0][1] + acc[1][1]) + (acc[2][1] + acc[3][1]);
        float s2 = (acc[0][2] + acc[1][2]) + (acc[2][2] + acc[3][2]);
        float s3 = (acc[0][3] + acc[1][3]) + (acc[2][3] + acc[3][3]);

        // ---- epilogue: x_new = 0.8*x_post + 0.2*acc + drive; store x_seq ----
        x0 = (1.f - ALPHA_N) * xp0 + ALPHA_N * s0 + d0.x;
        x1 = (1.f - ALPHA_N) * xp1 + ALPHA_N * s1 + d0.y;
        x2 = (1.f - ALPHA_N) * xp2 + ALPHA_N * s2 + d1.x;
        x3 = (1.f - ALPHA_N) * xp3 + ALPHA_N * s3 + d1.y;
        *reinterpret_cast<float2*>(&out_x[((size_t)br0 * T_STEPS + ts) * NH + hb]) = make_float2(x0, x1);
        *reinterpret_cast<float2*>(&out_x[((size_t)br1 * T_STEPS + ts) * NH + hb]) = make_float2(x2, x3);
        // next step's pre-publish __syncthreads guards rp reuse.
    }
}

// ---------------- y = relu(x) @ w_out_eff + b_out --------------------------
// one row per warp (max MLP); w_out in registers (no LDS).
__global__ void __launch_bounds__(256) y_kernel(const float* __restrict__ out_x,
                                                const float* __restrict__ b_out)
{
    int w = threadIdx.x >> 5, lane = threadIdx.x & 31;

    // lane owns h = k*128 + lane*4 + j  (k<4, j<4)
    float wr[4][4][3];
    #pragma unroll
    for (int k = 0; k < 4; k++)
        #pragma unroll
        for (int j = 0; j < 4; j++) {
            int h = k * 128 + lane * 4 + j;
            wr[k][j][0] = g_wout[h * 3 + 0];
            wr[k][j][1] = g_wout[h * 3 + 1];
            wr[k][j][2] = g_wout[h * 3 + 2];
        }

    int row = blockIdx.x * 8 + w;           // t*256 + b, rows 0..76799
    int t = row >> 8;
    int b = row & 255;
    const float* xr = out_x + ((size_t)b * T_STEPS + t) * NH;

    float a0 = 0.f, a1 = 0.f, a2 = 0.f;
    #pragma unroll
    for (int k = 0; k < 4; k++) {
        float4 v = *reinterpret_cast<const float4*>(xr + k * 128 + lane * 4);
        float r0 = fmaxf(v.x, 0.f), r1 = fmaxf(v.y, 0.f);
        float r2 = fmaxf(v.z, 0.f), r3 = fmaxf(v.w, 0.f);
        a0 += r0 * wr[k][0][0] + r1 * wr[k][1][0] + r2 * wr[k][2][0] + r3 * wr[k][3][0];
        a1 += r0 * wr[k][0][1] + r1 * wr[k][1][1] + r2 * wr[k][2][1] + r3 * wr[k][3][1];
        a2 += r0 * wr[k][0][2] + r1 * wr[k][1][2] + r2 * wr[k][2][2] + r3 * wr[k][3][2];
    }
    #pragma unroll
    for (int off = 16; off > 0; off >>= 1) {
        a0 += __shfl_xor_sync(0xffffffffu, a0, off);
        a1 += __shfl_xor_sync(0xffffffffu, a1, off);
        a2 += __shfl_xor_sync(0xffffffffu, a2, off);
    }
    if (lane == 0) {
        size_t base = ((size_t)t * BATCH + b) * NOUT;
        g_yraw[base + 0] = a0 + b_out[0];
        g_yraw[base + 1] = a1 + b_out[1];
        g_yraw[base + 2] = a2 + b_out[2];
    }
}

// ---------------- softmax over batch axis ----------------------------------
__global__ void __launch_bounds__(256) softmax_kernel(float* __restrict__ out_y)
{
    __shared__ float red[256];
    int t = blockIdx.x;
    int b = threadIdx.x;
    float v[NOUT], e[NOUT];
    #pragma unroll
    for (int o = 0; o < NOUT; o++)
        v[o] = g_yraw[((size_t)t * BATCH + b) * NOUT + o];

    #pragma unroll
    for (int o = 0; o < NOUT; o++) {
        red[b] = v[o];
        __syncthreads();
        for (int s = 128; s > 0; s >>= 1) {
            if (b < s) red[b] = fmaxf(red[b], red[b + s]);
            __syncthreads();
        }
        float mx = red[0];
        __syncthreads();
        e[o] = expf(v[o] - mx);
        red[b] = e[o];
        __syncthreads();
        for (int s = 128; s > 0; s >>= 1) {
            if (b < s) red[b] += red[b + s];
            __syncthreads();
        }
        float sm = red[0];
        __syncthreads();
        out_y[((size_t)b * T_STEPS + t) * NOUT + o] = e[o] / sm;
    }
}

// ---------------- launch ----------------------------------------------------
extern "C" void kernel_launch(void* const* d_in, const int* in_sizes, int n_in,
                              void* d_out, int out_size)
{
    const float* input_data = (const float*)d_in[0];
    const float* noise      = (const float*)d_in[1];
    const float* x_init     = (const float*)d_in[2];
    const float* syn_x_init = (const float*)d_in[3];
    const float* syn_u_init = (const float*)d_in[4];
    const float* w_in       = (const float*)d_in[5];
    const float* w_in_mask  = (const float*)d_in[6];
    const float* w_rnn_base = (const float*)d_in[7];
    const float* conn_mask  = (const float*)d_in[8];
    const float* ei_matrix  = (const float*)d_in[9];
    const float* b_rnn      = (const float*)d_in[10];
    const float* w_out      = (const float*)d_in[11];
    const float* w_out_mask = (const float*)d_in[12];
    const float* b_out      = (const float*)d_in[13];
    const float* a_std      = (const float*)d_in[14];
    const float* a_stf      = (const float*)d_in[15];
    const float* Uv         = (const float*)d_in[16];
    const float* dynv       = (const float*)d_in[17];

    float* out   = (float*)d_out;
    float* out_y = out;
    float* out_x = out + Y_SIZE;

    prep_kernel<<<148, 256>>>(w_in, w_in_mask, w_rnn_base, conn_mask, ei_matrix,
                              w_out, w_out_mask);
    dim3 dgrid(76800 / 64, NH / 64);
    drive_gemm<<<dgrid, 256>>>(input_data, noise, b_rnn);
    step_kernel<<<128, 256>>>(x_init, syn_x_init, syn_u_init,
                              a_std, a_stf, Uv, dynv, out_x);
    y_kernel<<<76800 / 8, 256>>>(out_x, b_out);   // FIX: 9600 blocks (was 1200)
    softmax_kernel<<<T_STEPS, 256>>>(out_y);
}

// round 7
// speedup vs baseline: 1.1212x; 1.1212x over previous
#include <cuda_runtime.h>
#include <cuda_fp16.h>
#include <cstdint>

#define T_STEPS 300
#define BATCH   256
#define NIN     128
#define NH      512
#define NOUT    3
#define DTSEC   0.01f
#define ALPHA_N 0.2f

#define Y_SIZE (BATCH * T_STEPS * NOUT)

// ---------------- device scratch (static, allocation-free) ----------------
__device__ float     g_drive[(size_t)T_STEPS * BATCH * NH];   // 157 MB
__device__ uint32_t  g_wrnnp[(NH / 2) * NH];                  // packed half2 (k-pair x h)
__device__ uint32_t  g_winp[(NIN / 2) * NH];
__device__ float     g_wout[NH * NOUT];
__device__ __half    g_rpost[2 * BATCH * NH];                 // double-buffered activations
__device__ float     g_yraw[(size_t)T_STEPS * BATCH * NOUT];
__device__ unsigned  g_bar[16 * T_STEPS];                     // per (group, step) counters

__device__ __forceinline__ uint32_t smem_u32(const void* p) {
    uint32_t a;
    asm("{ .reg .u64 t; cvta.to.shared.u64 t, %1; cvt.u32.u64 %0, t; }" : "=r"(a) : "l"(p));
    return a;
}

// ---------------- prep -----------------------------------------------------
__global__ void prep_kernel(const float* __restrict__ w_in, const float* __restrict__ w_in_mask,
                            const float* __restrict__ w_rnn_base, const float* __restrict__ conn,
                            const float* __restrict__ ei, const float* __restrict__ w_out,
                            const float* __restrict__ w_out_mask)
{
    int tid = blockIdx.x * blockDim.x + threadIdx.x;
    int nth = gridDim.x * blockDim.x;

    for (int i = tid; i < (NH / 2) * NH; i += nth) {
        int p = i >> 9, h = i & (NH - 1);
        int k0 = 2 * p, k1 = 2 * p + 1;
        float s0 = ei[k0 * NH + k0];
        float s1 = ei[k1 * NH + k1];
        float v0 = fmaxf(w_rnn_base[k0 * NH + h] * conn[k0 * NH + h], 0.f) * s0;
        float v1 = fmaxf(w_rnn_base[k1 * NH + h] * conn[k1 * NH + h], 0.f) * s1;
        __half2 hv = __floats2half2_rn(v0, v1);
        g_wrnnp[i] = *reinterpret_cast<uint32_t*>(&hv);
    }
    for (int i = tid; i < (NIN / 2) * NH; i += nth) {
        int p = i >> 9, h = i & (NH - 1);
        float v0 = w_in[(2 * p) * NH + h] * w_in_mask[(2 * p) * NH + h];
        float v1 = w_in[(2 * p + 1) * NH + h] * w_in_mask[(2 * p + 1) * NH + h];
        __half2 hv = __floats2half2_rn(v0, v1);
        g_winp[i] = *reinterpret_cast<uint32_t*>(&hv);
    }
    for (int i = tid; i < NH * NOUT; i += nth)
        g_wout[i] = fmaxf(w_out[i] * w_out_mask[i], 0.f);
    for (int i = tid; i < 16 * T_STEPS; i += nth)
        g_bar[i] = 0u;
}

// ---------------- drive GEMM: drive = 0.2*(inp@w_in_eff + b_rnn) + noise ---
__global__ void __launch_bounds__(256) drive_gemm(const float* __restrict__ inp,
                                                  const float* __restrict__ noise,
                                                  const float* __restrict__ b_rnn)
{
    __shared__ __half   a_s[64 * 136];
    __shared__ uint32_t b_s[64 * 68];

    int row0 = blockIdx.x * 64;
    int n0   = blockIdx.y * 64;
    int tid  = threadIdx.x;

    #pragma unroll
    for (int j = 0; j < 32; j++) {
        int idx = tid + j * 256;
        int i = idx >> 7, k = idx & 127;
        a_s[i * 136 + k] = __float2half_rn(inp[(size_t)(row0 + i) * NIN + k]);
    }
    #pragma unroll
    for (int j = 0; j < 16; j++) {
        int idx = tid + j * 256;
        int p = idx >> 6, c = idx & 63;
        b_s[p * 68 + c] = g_winp[p * NH + n0 + c];
    }
    __syncthreads();

    int w = tid >> 5, lane = tid & 31;
    int g = lane >> 2, t = lane & 3;
    int m0 = (w & 3) * 16;
    int nw = (w >> 2) * 32;

    float acc[4][4] = {};
    #pragma unroll
    for (int kk = 0; kk < 8; kk++) {
        int k0 = kk * 16;
        uint32_t a0 = *reinterpret_cast<const uint32_t*>(&a_s[(m0 + g) * 136 + k0 + 2 * t]);
        uint32_t a1 = *reinterpret_cast<const uint32_t*>(&a_s[(m0 + g + 8) * 136 + k0 + 2 * t]);
        uint32_t a2 = *reinterpret_cast<const uint32_t*>(&a_s[(m0 + g) * 136 + k0 + 8 + 2 * t]);
        uint32_t a3 = *reinterpret_cast<const uint32_t*>(&a_s[(m0 + g + 8) * 136 + k0 + 8 + 2 * t]);
        #pragma unroll
        for (int s = 0; s < 4; s++) {
            int col = nw + 8 * s + g;
            uint32_t b0 = b_s[(kk * 8 + t) * 68 + col];
            uint32_t b1 = b_s[(kk * 8 + t + 4) * 68 + col];
            asm volatile("mma.sync.aligned.m16n8k16.row.col.f32.f16.f16.f32 "
                         "{%0,%1,%2,%3}, {%4,%5,%6,%7}, {%8,%9}, {%0,%1,%2,%3};"
                         : "+f"(acc[s][0]), "+f"(acc[s][1]), "+f"(acc[s][2]), "+f"(acc[s][3])
                         : "r"(a0), "r"(a1), "r"(a2), "r"(a3), "r"(b0), "r"(b1));
        }
    }

    #pragma unroll
    for (int s = 0; s < 4; s++) {
        int gc  = n0 + nw + 8 * s + 2 * t;
        float br0 = b_rnn[gc], br1 = b_rnn[gc + 1];
        int r0 = row0 + m0 + g;
        int r1 = r0 + 8;
        float2 nz0 = *reinterpret_cast<const float2*>(&noise[(size_t)r0 * NH + gc]);
        float2 nz1 = *reinterpret_cast<const float2*>(&noise[(size_t)r1 * NH + gc]);
        float2 d0, d1;
        d0.x = ALPHA_N * (acc[s][0] + br0) + nz0.x;
        d0.y = ALPHA_N * (acc[s][1] + br1) + nz0.y;
        d1.x = ALPHA_N * (acc[s][2] + br0) + nz1.x;
        d1.y = ALPHA_N * (acc[s][3] + br1) + nz1.y;
        *reinterpret_cast<float2*>(&g_drive[(size_t)r0 * NH + gc]) = d0;
        *reinterpret_cast<float2*>(&g_drive[(size_t)r1 * NH + gc]) = d1;
    }
}

// ---------------- STP elementwise helper -----------------------------------
__device__ __forceinline__ void stp_phase1(
    const float x[4], float sx[4], float su[4],
    float as0, float as1, float af0, float af1,
    float U0, float U1, float dy0, float dy1,
    float xp[4])
{
    #pragma unroll
    for (int e = 0; e < 4; e++) {
        float as_ = (e & 1) ? as1 : as0;
        float af_ = (e & 1) ? af1 : af0;
        float U_  = (e & 1) ? U1  : U0;
        float dy_ = (e & 1) ? dy1 : dy0;
        float r = fmaxf(x[e], 0.f);
        float sxn = sx[e] + (as_ * (1.f - sx[e]) - DTSEC * su[e] * sx[e] * r) * dy_;
        float sun = su[e] + (af_ * (U_ - su[e]) + DTSEC * U_ * (1.f - su[e]) * r) * dy_;
        sx[e] = fminf(fmaxf(sxn, 0.f), 1.f);
        su[e] = fminf(fmaxf(sun, 0.f), 1.f);
        xp[e] = su[e] * sx[e] * x[e];
    }
}

// ---------------- persistent step kernel -----------------------------------
// 64 CTAs = 8 group-pairs x 8 h-slices. Each CTA serves TWO batch groups
// (A = 2*pair, B = 2*pair+1) with the same h-slice: B-fragments shared in
// registers; A's barrier latency hidden under B's work and vice versa.
__global__ void __launch_bounds__(256, 1) step_kernel(
    const float* __restrict__ x_init, const float* __restrict__ sx_init,
    const float* __restrict__ su_init,
    const float* __restrict__ a_std, const float* __restrict__ a_stf,
    const float* __restrict__ Uv, const float* __restrict__ dynv,
    float* __restrict__ out_x)
{
    __shared__ __half rp[2][16 * 520];   // staged rpost tile per group

    int cta   = blockIdx.x;              // 0..63
    int pair  = cta >> 3;
    int slice = cta & 7;
    int grp0 = pair * 2;
    int h0 = slice * 64;
    int tid = threadIdx.x;
    int w = tid >> 5, lane = tid & 31;
    int g = lane >> 2, t = lane & 3;

    // ---- persistent B fragments for W_rnn slice (shared by both groups) ----
    uint32_t breg0[32], breg1[32];
    {
        int c = h0 + 8 * w + g;
        #pragma unroll
        for (int kk = 0; kk < 32; kk++) {
            breg0[kk] = g_wrnnp[(size_t)(kk * 8 + t) * NH + c];
            breg1[kk] = g_wrnnp[(size_t)(kk * 8 + t + 4) * NH + c];
        }
    }

    int hb = h0 + 8 * w + 2 * t;

    float as0 = a_std[hb], as1 = a_std[hb + 1];
    float af0 = a_stf[hb], af1 = a_stf[hb + 1];
    float U0  = Uv[hb],    U1  = Uv[hb + 1];
    float dy0 = dynv[hb],  dy1 = dynv[hb + 1];

    // per-group state: rows br0 = b0+g, br1 = b0+g+8
    float X[2][4], SX[2][4], SU[2][4], XP[2][4];
    int BR0[2], BR1[2];
    #pragma unroll
    for (int gi = 0; gi < 2; gi++) {
        int b0 = (grp0 + gi) * 16;
        int br0 = b0 + g, br1 = b0 + g + 8;
        BR0[gi] = br0; BR1[gi] = br1;
        X[gi][0]  = x_init[br0 * NH + hb];   X[gi][1]  = x_init[br0 * NH + hb + 1];
        X[gi][2]  = x_init[br1 * NH + hb];   X[gi][3]  = x_init[br1 * NH + hb + 1];
        SX[gi][0] = sx_init[br0 * NH + hb];  SX[gi][1] = sx_init[br0 * NH + hb + 1];
        SX[gi][2] = sx_init[br1 * NH + hb];  SX[gi][3] = sx_init[br1 * NH + hb + 1];
        SU[gi][0] = su_init[br0 * NH + hb];  SU[gi][1] = su_init[br0 * NH + hb + 1];
        SU[gi][2] = su_init[br1 * NH + hb];  SU[gi][3] = su_init[br1 * NH + hb + 1];
    }

    __half2* rgl = reinterpret_cast<__half2*>(g_rpost);

    uint32_t lds_a0 = smem_u32(rp[0]) + (lane & 15) * (520 * 2) + ((lane >> 4) & 1) * 16;

    // staging geometry (shared): idx = tid + j*256 -> row = idx>>6, c8 = idx&63
    // drive prefetch registers (hold step ts)
    float2 DPF[2][2];
    #pragma unroll
    for (int gi = 0; gi < 2; gi++) {
        DPF[gi][0] = *reinterpret_cast<const float2*>(&g_drive[(size_t)BR0[gi] * NH + hb]);
        DPF[gi][1] = *reinterpret_cast<const float2*>(&g_drive[(size_t)BR1[gi] * NH + hb]);
    }

    // ---- prologue: phase1 + publish rpost for ts=0, both groups ----
    #pragma unroll
    for (int gi = 0; gi < 2; gi++) {
        stp_phase1(X[gi], SX[gi], SU[gi], as0, as1, af0, af1, U0, U1, dy0, dy1, XP[gi]);
        rgl[(0 * BATCH * NH + BR0[gi] * NH + hb) >> 1] =
            __floats2half2_rn(fmaxf(XP[gi][0], 0.f), fmaxf(XP[gi][1], 0.f));
        rgl[(0 * BATCH * NH + BR1[gi] * NH + hb) >> 1] =
            __floats2half2_rn(fmaxf(XP[gi][2], 0.f), fmaxf(XP[gi][3], 0.f));
    }
    __syncthreads();
    if (tid == 0) {
        #pragma unroll
        for (int gi = 0; gi < 2; gi++)
            asm volatile("red.release.gpu.global.add.u32 [%0], %1;"
                         :: "l"(&g_bar[(grp0 + gi) * T_STEPS]), "r"(1u) : "memory");
    }

    for (int ts = 0; ts < T_STEPS; ts++) {
        int buf  = ts & 1;
        int tsn  = (ts + 1 < T_STEPS) ? ts + 1 : ts;
        bool more = (ts + 1 < T_STEPS);

        #pragma unroll
        for (int gi = 0; gi < 2; gi++) {
            int grp = grp0 + gi;
            int b0  = grp * 16;

            // ---- prefetch drive for ts+1 (consumed next iteration) ----
            float2 nd0 = *reinterpret_cast<const float2*>(
                &g_drive[((size_t)tsn * BATCH + BR0[gi]) * NH + hb]);
            float2 nd1 = *reinterpret_cast<const float2*>(
                &g_drive[((size_t)tsn * BATCH + BR1[gi]) * NH + hb]);

            // ---- wait: single poller + syncthreads ----
            if (tid == 0) {
                unsigned* c = &g_bar[grp * T_STEPS + ts];
                unsigned v;
                do {
                    asm volatile("ld.acquire.gpu.global.u32 %0, [%1];"
                                 : "=r"(v) : "l"(c) : "memory");
                } while (v < 8u);
            }
            __syncthreads();

            // ---- stage rpost [16][512] fp16 via L2 (.cg skips L1) ----
            {
                const uint4* src = reinterpret_cast<const uint4*>(g_rpost + buf * BATCH * NH);
                __half* dst = rp[gi];
                #pragma unroll
                for (int j = 0; j < 4; j++) {
                    int idx = tid + j * 256;
                    int row = idx >> 6, c8 = idx & 63;
                    uint4 v;
                    asm volatile("ld.global.cg.v4.u32 {%0,%1,%2,%3}, [%4];"
                                 : "=r"(v.x), "=r"(v.y), "=r"(v.z), "=r"(v.w)
                                 : "l"(src + (size_t)(b0 + row) * 64 + c8));
                    *reinterpret_cast<uint4*>(dst + row * 520 + c8 * 8) = v;
                }
            }
            __syncthreads();

            // ---- mma: C[16x64] = rpost[16x512] @ W[512x64]; 4 acc chains ----
            uint32_t lds_a = lds_a0 + gi * (16 * 520 * 2);
            float acc[4][4] = {};
            #pragma unroll
            for (int kk = 0; kk < 32; kk++) {
                uint32_t a0, a1, a2, a3;
                asm volatile("ldmatrix.sync.aligned.m8n8.x4.shared.b16 {%0,%1,%2,%3}, [%4];"
                             : "=r"(a0), "=r"(a1), "=r"(a2), "=r"(a3)
                             : "r"(lds_a + kk * 32));
                float* A = acc[kk & 3];
                asm volatile("mma.sync.aligned.m16n8k16.row.col.f32.f16.f16.f32 "
                             "{%0,%1,%2,%3}, {%4,%5,%6,%7}, {%8,%9}, {%0,%1,%2,%3};"
                             : "+f"(A[0]), "+f"(A[1]), "+f"(A[2]), "+f"(A[3])
                             : "r"(a0), "r"(a1), "r"(a2), "r"(a3), "r"(breg0[kk]), "r"(breg1[kk]));
            }
            float s0 = (acc[0][0] + acc[1][0]) + (acc[2][0] + acc[3][0]);
            float s1 = (acc[0][1] + acc[1][1]) + (acc[2][1] + acc[3][1]);
            float s2 = (acc[0][2] + acc[1][2]) + (acc[2][2] + acc[3][2]);
            float s3 = (acc[0][3] + acc[1][3]) + (acc[2][3] + acc[3][3]);

            // ---- epilogue: x_new; write x_seq ----
            X[gi][0] = (1.f - ALPHA_N) * XP[gi][0] + ALPHA_N * s0 + DPF[gi][0].x;
            X[gi][1] = (1.f - ALPHA_N) * XP[gi][1] + ALPHA_N * s1 + DPF[gi][0].y;
            X[gi][2] = (1.f - ALPHA_N) * XP[gi][2] + ALPHA_N * s2 + DPF[gi][1].x;
            X[gi][3] = (1.f - ALPHA_N) * XP[gi][3] + ALPHA_N * s3 + DPF[gi][1].y;
            *reinterpret_cast<float2*>(&out_x[((size_t)BR0[gi] * T_STEPS + ts) * NH + hb]) =
                make_float2(X[gi][0], X[gi][1]);
            *reinterpret_cast<float2*>(&out_x[((size_t)BR1[gi] * T_STEPS + ts) * NH + hb]) =
                make_float2(X[gi][2], X[gi][3]);
            DPF[gi][0] = nd0;
            DPF[gi][1] = nd1;

            // ---- phase1(ts+1) + publish ----
            if (more) {
                stp_phase1(X[gi], SX[gi], SU[gi], as0, as1, af0, af1, U0, U1, dy0, dy1, XP[gi]);
                int nbuf = buf ^ 1;
                rgl[(nbuf * BATCH * NH + BR0[gi] * NH + hb) >> 1] =
                    __floats2half2_rn(fmaxf(XP[gi][0], 0.f), fmaxf(XP[gi][1], 0.f));
                rgl[(nbuf * BATCH * NH + BR1[gi] * NH + hb) >> 1] =
                    __floats2half2_rn(fmaxf(XP[gi][2], 0.f), fmaxf(XP[gi][3], 0.f));
                __syncthreads();   // all rpost stores done + rp[gi] reuse guard
                if (tid == 0)
                    asm volatile("red.release.gpu.global.add.u32 [%0], %1;"
                                 :: "l"(&g_bar[grp * T_STEPS + ts + 1]), "r"(1u) : "memory");
            }
        }
    }
}

// ---------------- y = relu(x) @ w_out_eff + b_out (R3 version) -------------
__global__ void __launch_bounds__(256) y_kernel(const float* __restrict__ out_x,
                                                const float* __restrict__ b_out)
{
    __shared__ float wsh[NH * NOUT];
    for (int i = threadIdx.x; i < NH * NOUT; i += 256) wsh[i] = g_wout[i];
    __syncthreads();

    int w = threadIdx.x >> 5, lane = threadIdx.x & 31;
    int row = blockIdx.x * 8 + w;           // t*256 + b
    int t = row >> 8;
    int b = row & 255;
    const float* xr = out_x + ((size_t)b * T_STEPS + t) * NH;

    float a0 = 0.f, a1 = 0.f, a2 = 0.f;
    #pragma unroll 4
    for (int h = lane; h < NH; h += 32) {
        float r = fmaxf(xr[h], 0.f);
        a0 += r * wsh[h * 3 + 0];
        a1 += r * wsh[h * 3 + 1];
        a2 += r * wsh[h * 3 + 2];
    }
    #pragma unroll
    for (int off = 16; off > 0; off >>= 1) {
        a0 += __shfl_xor_sync(0xffffffffu, a0, off);
        a1 += __shfl_xor_sync(0xffffffffu, a1, off);
        a2 += __shfl_xor_sync(0xffffffffu, a2, off);
    }
    if (lane == 0) {
        size_t base = ((size_t)t * BATCH + b) * NOUT;
        g_yraw[base + 0] = a0 + b_out[0];
        g_yraw[base + 1] = a1 + b_out[1];
        g_yraw[base + 2] = a2 + b_out[2];
    }
}

// ---------------- softmax over batch axis ----------------------------------
__global__ void __launch_bounds__(256) softmax_kernel(float* __restrict__ out_y)
{
    __shared__ float red[256];
    int t = blockIdx.x;
    int b = threadIdx.x;
    float v[NOUT], e[NOUT];
    #pragma unroll
    for (int o = 0; o < NOUT; o++)
        v[o] = g_yraw[((size_t)t * BATCH + b) * NOUT + o];

    #pragma unroll
    for (int o = 0; o < NOUT; o++) {
        red[b] = v[o];
        __syncthreads();
        for (int s = 128; s > 0; s >>= 1) {
            if (b < s) red[b] = fmaxf(red[b], red[b + s]);
            __syncthreads();
        }
        float mx = red[0];
        __syncthreads();
        e[o] = expf(v[o] - mx);
        red[b] = e[o];
        __syncthreads();
        for (int s = 128; s > 0; s >>= 1) {
            if (b < s) red[b] += red[b + s];
            __syncthreads();
        }
        float sm = red[0];
        __syncthreads();
        out_y[((size_t)b * T_STEPS + t) * NOUT + o] = e[o] / sm;
    }
}

// ---------------- launch ----------------------------------------------------
extern "C" void kernel_launch(void* const* d_in, const int* in_sizes, int n_in,
                              void* d_out, int out_size)
{
    const float* input_data = (const float*)d_in[0];
    const float* noise      = (const float*)d_in[1];
    const float* x_init     = (const float*)d_in[2];
    const float* syn_x_init = (const float*)d_in[3];
    const float* syn_u_init = (const float*)d_in[4];
    const float* w_in       = (const float*)d_in[5];
    const float* w_in_mask  = (const float*)d_in[6];
    const float* w_rnn_base = (const float*)d_in[7];
    const float* conn_mask  = (const float*)d_in[8];
    const float* ei_matrix  = (const float*)d_in[9];
    const float* b_rnn      = (const float*)d_in[10];
    const float* w_out      = (const float*)d_in[11];
    const float* w_out_mask = (const float*)d_in[12];
    const float* b_out      = (const float*)d_in[13];
    const float* a_std      = (const float*)d_in[14];
    const float* a_stf      = (const float*)d_in[15];
    const float* Uv         = (const float*)d_in[16];
    const float* dynv       = (const float*)d_in[17];

    float* out   = (float*)d_out;
    float* out_y = out;
    float* out_x = out + Y_SIZE;

    prep_kernel<<<148, 256>>>(w_in, w_in_mask, w_rnn_base, conn_mask, ei_matrix,
                              w_out, w_out_mask);
    dim3 dgrid(76800 / 64, NH / 64);
    drive_gemm<<<dgrid, 256>>>(input_data, noise, b_rnn);
    step_kernel<<<64, 256>>>(x_init, syn_x_init, syn_u_init,
                             a_std, a_stf, Uv, dynv, out_x);
    y_kernel<<<76800 / 8, 256>>>(out_x, b_out);
    softmax_kernel<<<T_STEPS, 256>>>(out_y);
}

// round 9
// speedup vs baseline: 1.8229x; 1.6258x over previous
#include <cuda_runtime.h>
#include <cuda_fp16.h>
#include <cstdint>

#define T_STEPS 300
#define BATCH   256
#define NIN     128
#define NH      512
#define NOUT    3
#define DTSEC   0.01f
#define ALPHA_N 0.2f

#define Y_SIZE (BATCH * T_STEPS * NOUT)
#define TS_PAD 304

// ---------------- device scratch (static, allocation-free) ----------------
__device__ float     g_drive[(size_t)T_STEPS * BATCH * NH];   // 157 MB
__device__ uint32_t  g_wrnnp[(NH / 2) * NH];                  // packed half2 (k-pair x h)
__device__ uint32_t  g_winp[(NIN / 2) * NH];
__device__ float     g_wout[NH * NOUT];
__device__ __half    g_rpost[2 * BATCH * NH];                 // double-buffered activations
__device__ float     g_yraw[(size_t)T_STEPS * BATCH * NOUT];
__device__ unsigned  g_flag[16 * 8 * TS_PAD];                 // per (group, slice, step)

__device__ __forceinline__ uint32_t smem_u32(const void* p) {
    uint32_t a;
    asm("{ .reg .u64 t; cvta.to.shared.u64 t, %1; cvt.u32.u64 %0, t; }" : "=r"(a) : "l"(p));
    return a;
}

// ---------------- prep -----------------------------------------------------
__global__ void prep_kernel(const float* __restrict__ w_in, const float* __restrict__ w_in_mask,
                            const float* __restrict__ w_rnn_base, const float* __restrict__ conn,
                            const float* __restrict__ ei, const float* __restrict__ w_out,
                            const float* __restrict__ w_out_mask)
{
    int tid = blockIdx.x * blockDim.x + threadIdx.x;
    int nth = gridDim.x * blockDim.x;

    for (int i = tid; i < (NH / 2) * NH; i += nth) {
        int p = i >> 9, h = i & (NH - 1);
        int k0 = 2 * p, k1 = 2 * p + 1;
        float s0 = ei[k0 * NH + k0];
        float s1 = ei[k1 * NH + k1];
        float v0 = fmaxf(w_rnn_base[k0 * NH + h] * conn[k0 * NH + h], 0.f) * s0;
        float v1 = fmaxf(w_rnn_base[k1 * NH + h] * conn[k1 * NH + h], 0.f) * s1;
        __half2 hv = __floats2half2_rn(v0, v1);
        g_wrnnp[i] = *reinterpret_cast<uint32_t*>(&hv);
    }
    for (int i = tid; i < (NIN / 2) * NH; i += nth) {
        int p = i >> 9, h = i & (NH - 1);
        float v0 = w_in[(2 * p) * NH + h] * w_in_mask[(2 * p) * NH + h];
        float v1 = w_in[(2 * p + 1) * NH + h] * w_in_mask[(2 * p + 1) * NH + h];
        __half2 hv = __floats2half2_rn(v0, v1);
        g_winp[i] = *reinterpret_cast<uint32_t*>(&hv);
    }
    for (int i = tid; i < NH * NOUT; i += nth)
        g_wout[i] = fmaxf(w_out[i] * w_out_mask[i], 0.f);
    for (int i = tid; i < 16 * 8 * TS_PAD; i += nth)
        g_flag[i] = 0u;
}

// ---------------- drive GEMM: drive = 0.2*(inp@w_in_eff + b_rnn) + noise ---
__global__ void __launch_bounds__(256) drive_gemm(const float* __restrict__ inp,
                                                  const float* __restrict__ noise,
                                                  const float* __restrict__ b_rnn)
{
    __shared__ __half   a_s[64 * 136];
    __shared__ uint32_t b_s[64 * 68];

    int row0 = blockIdx.x * 64;
    int n0   = blockIdx.y * 64;
    int tid  = threadIdx.x;

    #pragma unroll
    for (int j = 0; j < 32; j++) {
        int idx = tid + j * 256;
        int i = idx >> 7, k = idx & 127;
        a_s[i * 136 + k] = __float2half_rn(inp[(size_t)(row0 + i) * NIN + k]);
    }
    #pragma unroll
    for (int j = 0; j < 16; j++) {
        int idx = tid + j * 256;
        int p = idx >> 6, c = idx & 63;
        b_s[p * 68 + c] = g_winp[p * NH + n0 + c];
    }
    __syncthreads();

    int w = tid >> 5, lane = tid & 31;
    int g = lane >> 2, t = lane & 3;
    int m0 = (w & 3) * 16;
    int nw = (w >> 2) * 32;

    float acc[4][4] = {};
    #pragma unroll
    for (int kk = 0; kk < 8; kk++) {
        int k0 = kk * 16;
        uint32_t a0 = *reinterpret_cast<const uint32_t*>(&a_s[(m0 + g) * 136 + k0 + 2 * t]);
        uint32_t a1 = *reinterpret_cast<const uint32_t*>(&a_s[(m0 + g + 8) * 136 + k0 + 2 * t]);
        uint32_t a2 = *reinterpret_cast<const uint32_t*>(&a_s[(m0 + g) * 136 + k0 + 8 + 2 * t]);
        uint32_t a3 = *reinterpret_cast<const uint32_t*>(&a_s[(m0 + g + 8) * 136 + k0 + 8 + 2 * t]);
        #pragma unroll
        for (int s = 0; s < 4; s++) {
            int col = nw + 8 * s + g;
            uint32_t b0 = b_s[(kk * 8 + t) * 68 + col];
            uint32_t b1 = b_s[(kk * 8 + t + 4) * 68 + col];
            asm volatile("mma.sync.aligned.m16n8k16.row.col.f32.f16.f16.f32 "
                         "{%0,%1,%2,%3}, {%4,%5,%6,%7}, {%8,%9}, {%0,%1,%2,%3};"
                         : "+f"(acc[s][0]), "+f"(acc[s][1]), "+f"(acc[s][2]), "+f"(acc[s][3])
                         : "r"(a0), "r"(a1), "r"(a2), "r"(a3), "r"(b0), "r"(b1));
        }
    }

    #pragma unroll
    for (int s = 0; s < 4; s++) {
        int gc  = n0 + nw + 8 * s + 2 * t;
        float br0 = b_rnn[gc], br1 = b_rnn[gc + 1];
        int r0 = row0 + m0 + g;
        int r1 = r0 + 8;
        float2 nz0 = *reinterpret_cast<const float2*>(&noise[(size_t)r0 * NH + gc]);
        float2 nz1 = *reinterpret_cast<const float2*>(&noise[(size_t)r1 * NH + gc]);
        float2 d0, d1;
        d0.x = ALPHA_N * (acc[s][0] + br0) + nz0.x;
        d0.y = ALPHA_N * (acc[s][1] + br1) + nz0.y;
        d1.x = ALPHA_N * (acc[s][2] + br0) + nz1.x;
        d1.y = ALPHA_N * (acc[s][3] + br1) + nz1.y;
        *reinterpret_cast<float2*>(&g_drive[(size_t)r0 * NH + gc]) = d0;
        *reinterpret_cast<float2*>(&g_drive[(size_t)r1 * NH + gc]) = d1;
    }
}

// ---------------- persistent step kernel -----------------------------------
// 128 CTAs = 16 b-groups x 8 h-slices. W_rnn B-fragments in registers.
// Signaling: per-slice single-writer release flags; each warp polls only the
// flag of the slice it stages (8 pollers/line), staging pipelined per slice.
__global__ void __launch_bounds__(256, 1) step_kernel(
    const float* __restrict__ x_init, const float* __restrict__ sx_init,
    const float* __restrict__ su_init,
    const float* __restrict__ a_std, const float* __restrict__ a_stf,
    const float* __restrict__ Uv, const float* __restrict__ dynv,
    float* __restrict__ out_x)
{
    __shared__ __half rp[16 * 520];      // staged rpost tile [16][520]

    int cta   = blockIdx.x;
    int grp   = cta >> 3;
    int slice = cta & 7;
    int b0 = grp * 16;
    int h0 = slice * 64;
    int tid = threadIdx.x;
    int w = tid >> 5, lane = tid & 31;
    int g = lane >> 2, t = lane & 3;

    // ---- persistent B fragments for W_rnn slice (registers, step-invariant)
    uint32_t breg0[32], breg1[32];
    {
        int c = h0 + 8 * w + g;
        #pragma unroll
        for (int kk = 0; kk < 32; kk++) {
            breg0[kk] = g_wrnnp[(size_t)(kk * 8 + t) * NH + c];
            breg1[kk] = g_wrnnp[(size_t)(kk * 8 + t + 4) * NH + c];
        }
    }

    int hb  = h0 + 8 * w + 2 * t;
    int br0 = b0 + g, br1 = b0 + g + 8;

    float as0 = a_std[hb], as1 = a_std[hb + 1];
    float af0 = a_stf[hb], af1 = a_stf[hb + 1];
    float U0  = Uv[hb],    U1  = Uv[hb + 1];
    float dy0 = dynv[hb],  dy1 = dynv[hb + 1];

    float x0 = x_init[br0 * NH + hb],   x1 = x_init[br0 * NH + hb + 1];
    float x2 = x_init[br1 * NH + hb],   x3 = x_init[br1 * NH + hb + 1];
    float sx0 = sx_init[br0 * NH + hb], sx1 = sx_init[br0 * NH + hb + 1];
    float sx2 = sx_init[br1 * NH + hb], sx3 = sx_init[br1 * NH + hb + 1];
    float su0 = su_init[br0 * NH + hb], su1 = su_init[br0 * NH + hb + 1];
    float su2 = su_init[br1 * NH + hb], su3 = su_init[br1 * NH + hb + 1];

    __half2* rgl = reinterpret_cast<__half2*>(g_rpost);

    // ldmatrix lane address: row = lane&15, k-half offset for lanes 16-31
    uint32_t lds_a = smem_u32(rp) + (lane & 15) * (520 * 2) + ((lane >> 4) & 1) * 16;

    unsigned* my_flag   = g_flag + (grp * 8 + slice) * TS_PAD;   // producer stream
    unsigned* poll_flag = g_flag + (grp * 8 + w) * TS_PAD;       // warp w stages slice w

    for (int ts = 0; ts < T_STEPS; ts++) {
        // ---- prefetch drive early (consumed after MMA) ----
        float2 d0 = *reinterpret_cast<const float2*>(&g_drive[((size_t)ts * BATCH + br0) * NH + hb]);
        float2 d1 = *reinterpret_cast<const float2*>(&g_drive[((size_t)ts * BATCH + br1) * NH + hb]);

        // ---- phase 1: STP update + x_post + rpost ----
        float xp0, xp1, xp2, xp3;
        {
            float r, sxn, sun;
            r = fmaxf(x0, 0.f);
            sxn = sx0 + (as0 * (1.f - sx0) - DTSEC * su0 * sx0 * r) * dy0;
            sun = su0 + (af0 * (U0 - su0) + DTSEC * U0 * (1.f - su0) * r) * dy0;
            sx0 = fminf(fmaxf(sxn, 0.f), 1.f); su0 = fminf(fmaxf(sun, 0.f), 1.f);
            xp0 = su0 * sx0 * x0;

            r = fmaxf(x1, 0.f);
            sxn = sx1 + (as1 * (1.f - sx1) - DTSEC * su1 * sx1 * r) * dy1;
            sun = su1 + (af1 * (U1 - su1) + DTSEC * U1 * (1.f - su1) * r) * dy1;
            sx1 = fminf(fmaxf(sxn, 0.f), 1.f); su1 = fminf(fmaxf(sun, 0.f), 1.f);
            xp1 = su1 * sx1 * x1;

            r = fmaxf(x2, 0.f);
            sxn = sx2 + (as0 * (1.f - sx2) - DTSEC * su2 * sx2 * r) * dy0;
            sun = su2 + (af0 * (U0 - su2) + DTSEC * U0 * (1.f - su2) * r) * dy0;
            sx2 = fminf(fmaxf(sxn, 0.f), 1.f); su2 = fminf(fmaxf(sun, 0.f), 1.f);
            xp2 = su2 * sx2 * x2;

            r = fmaxf(x3, 0.f);
            sxn = sx3 + (as1 * (1.f - sx3) - DTSEC * su3 * sx3 * r) * dy1;
            sun = su3 + (af1 * (U1 - su3) + DTSEC * U1 * (1.f - su3) * r) * dy1;
            sx3 = fminf(fmaxf(sxn, 0.f), 1.f); su3 = fminf(fmaxf(sun, 0.f), 1.f);
            xp3 = su3 * sx3 * x3;
        }
        int buf = ts & 1;
        rgl[(buf * BATCH * NH + br0 * NH + hb) >> 1] =
            __floats2half2_rn(fmaxf(xp0, 0.f), fmaxf(xp1, 0.f));
        rgl[(buf * BATCH * NH + br1 * NH + hb) >> 1] =
            __floats2half2_rn(fmaxf(xp2, 0.f), fmaxf(xp3, 0.f));

        // ---- publish: single-writer release flag (no RMW) ----
        __syncthreads();     // all STGs issued; also guards rp reuse
        if (tid == 0)
            asm volatile("st.release.gpu.global.u32 [%0], %1;"
                         :: "l"(my_flag + ts), "r"(1u) : "memory");

        // ---- per-warp: poll slice w's flag, then stage its 2KB ----
        {
            if (w != slice && lane == 0) {
                unsigned v;
                do {
                    asm volatile("ld.acquire.gpu.global.u32 %0, [%1];"
                                 : "=r"(v) : "l"(poll_flag + ts) : "memory");
                } while (!v);
            }
            __syncwarp();
            const uint4* src = reinterpret_cast<const uint4*>(g_rpost + buf * BATCH * NH);
            #pragma unroll
            for (int i = 0; i < 4; i++) {
                int idx = lane + 32 * i;
                int row = idx >> 3, c8 = idx & 7;
                uint4 v;
                asm volatile("ld.global.cg.v4.u32 {%0,%1,%2,%3}, [%4];"
                             : "=r"(v.x), "=r"(v.y), "=r"(v.z), "=r"(v.w)
                             : "l"(src + (size_t)(b0 + row) * 64 + w * 8 + c8));
                *reinterpret_cast<uint4*>(rp + row * 520 + w * 64 + c8 * 8) = v;
            }
        }
        __syncthreads();

        // ---- mma: C[16x64] = rpost[16x512] @ W[512x64]; 4 accumulator chains
        float acc[4][4] = {};
        #pragma unroll
        for (int kk = 0; kk < 32; kk++) {
            uint32_t a0, a1, a2, a3;
            asm volatile("ldmatrix.sync.aligned.m8n8.x4.shared.b16 {%0,%1,%2,%3}, [%4];"
                         : "=r"(a0), "=r"(a1), "=r"(a2), "=r"(a3)
                         : "r"(lds_a + kk * 32));
            float* A = acc[kk & 3];
            asm volatile("mma.sync.aligned.m16n8k16.row.col.f32.f16.f16.f32 "
                         "{%0,%1,%2,%3}, {%4,%5,%6,%7}, {%8,%9}, {%0,%1,%2,%3};"
                         : "+f"(A[0]), "+f"(A[1]), "+f"(A[2]), "+f"(A[3])
                         : "r"(a0), "r"(a1), "r"(a2), "r"(a3), "r"(breg0[kk]), "r"(breg1[kk]));
        }
        float s0 = (acc[0][0] + acc[1][0]) + (acc[2][0] + acc[3][0]);
        float s1 = (acc[0][1] + acc[1][1]) + (acc[2][1] + acc[3][1]);
        float s2 = (acc[0][2] + acc[1][2]) + (acc[2][2] + acc[3][2]);
        float s3 = (acc[0][3] + acc[1][3]) + (acc[2][3] + acc[3][3]);

        // ---- epilogue: x_new = 0.8*x_post + 0.2*acc + drive; store x_seq ----
        x0 = (1.f - ALPHA_N) * xp0 + ALPHA_N * s0 + d0.x;
        x1 = (1.f - ALPHA_N) * xp1 + ALPHA_N * s1 + d0.y;
        x2 = (1.f - ALPHA_N) * xp2 + ALPHA_N * s2 + d1.x;
        x3 = (1.f - ALPHA_N) * xp3 + ALPHA_N * s3 + d1.y;
        *reinterpret_cast<float2*>(&out_x[((size_t)br0 * T_STEPS + ts) * NH + hb]) = make_float2(x0, x1);
        *reinterpret_cast<float2*>(&out_x[((size_t)br1 * T_STEPS + ts) * NH + hb]) = make_float2(x2, x3);
        // next step's pre-publish __syncthreads guards rp reuse.
    }
}

// ---------------- y = relu(x) @ w_out_eff + b_out (R3 version) -------------
__global__ void __launch_bounds__(256) y_kernel(const float* __restrict__ out_x,
                                                const float* __restrict__ b_out)
{
    __shared__ float wsh[NH * NOUT];
    for (int i = threadIdx.x; i < NH * NOUT; i += 256) wsh[i] = g_wout[i];
    __syncthreads();

    int w = threadIdx.x >> 5, lane = threadIdx.x & 31;
    int row = blockIdx.x * 8 + w;           // t*256 + b
    int t = row >> 8;
    int b = row & 255;
    const float* xr = out_x + ((size_t)b * T_STEPS + t) * NH;

    float a0 = 0.f, a1 = 0.f, a2 = 0.f;
    #pragma unroll 4
    for (int h = lane; h < NH; h += 32) {
        float r = fmaxf(xr[h], 0.f);
        a0 += r * wsh[h * 3 + 0];
        a1 += r * wsh[h * 3 + 1];
        a2 += r * wsh[h * 3 + 2];
    }
    #pragma unroll
    for (int off = 16; off > 0; off >>= 1) {
        a0 += __shfl_xor_sync(0xffffffffu, a0, off);
        a1 += __shfl_xor_sync(0xffffffffu, a1, off);
        a2 += __shfl_xor_sync(0xffffffffu, a2, off);
    }
    if (lane == 0) {
        size_t base = ((size_t)t * BATCH + b) * NOUT;
        g_yraw[base + 0] = a0 + b_out[0];
        g_yraw[base + 1] = a1 + b_out[1];
        g_yraw[base + 2] = a2 + b_out[2];
    }
}

// ---------------- softmax over batch axis ----------------------------------
__global__ void __launch_bounds__(256) softmax_kernel(float* __restrict__ out_y)
{
    __shared__ float red[256];
    int t = blockIdx.x;
    int b = threadIdx.x;
    float v[NOUT], e[NOUT];
    #pragma unroll
    for (int o = 0; o < NOUT; o++)
        v[o] = g_yraw[((size_t)t * BATCH + b) * NOUT + o];

    #pragma unroll
    for (int o = 0; o < NOUT; o++) {
        red[b] = v[o];
        __syncthreads();
        for (int s = 128; s > 0; s >>= 1) {
            if (b < s) red[b] = fmaxf(red[b], red[b + s]);
            __syncthreads();
        }
        float mx = red[0];
        __syncthreads();
        e[o] = expf(v[o] - mx);
        red[b] = e[o];
        __syncthreads();
        for (int s = 128; s > 0; s >>= 1) {
            if (b < s) red[b] += red[b + s];
            __syncthreads();
        }
        float sm = red[0];
        __syncthreads();
        out_y[((size_t)b * T_STEPS + t) * NOUT + o] = e[o] / sm;
    }
}

// ---------------- launch ----------------------------------------------------
extern "C" void kernel_launch(void* const* d_in, const int* in_sizes, int n_in,
                              void* d_out, int out_size)
{
    const float* input_data = (const float*)d_in[0];
    const float* noise      = (const float*)d_in[1];
    const float* x_init     = (const float*)d_in[2];
    const float* syn_x_init = (const float*)d_in[3];
    const float* syn_u_init = (const float*)d_in[4];
    const float* w_in       = (const float*)d_in[5];
    const float* w_in_mask  = (const float*)d_in[6];
    const float* w_rnn_base = (const float*)d_in[7];
    const float* conn_mask  = (const float*)d_in[8];
    const float* ei_matrix  = (const float*)d_in[9];
    const float* b_rnn      = (const float*)d_in[10];
    const float* w_out      = (const float*)d_in[11];
    const float* w_out_mask = (const float*)d_in[12];
    const float* b_out      = (const float*)d_in[13];
    const float* a_std      = (const float*)d_in[14];
    const float* a_stf      = (const float*)d_in[15];
    const float* Uv         = (const float*)d_in[16];
    const float* dynv       = (const float*)d_in[17];

    float* out   = (float*)d_out;
    float* out_y = out;
    float* out_x = out + Y_SIZE;

    prep_kernel<<<148, 256>>>(w_in, w_in_mask, w_rnn_base, conn_mask, ei_matrix,
                              w_out, w_out_mask);
    dim3 dgrid(76800 / 64, NH / 64);
    drive_gemm<<<dgrid, 256>>>(input_data, noise, b_rnn);
    step_kernel<<<128, 256>>>(x_init, syn_x_init, syn_u_init,
                              a_std, a_stf, Uv, dynv, out_x);
    y_kernel<<<76800 / 8, 256>>>(out_x, b_out);
    softmax_kernel<<<T_STEPS, 256>>>(out_y);
}